// round 2
// baseline (speedup 1.0000x reference)
#include <cuda_runtime.h>
#include <math.h>

#define FDIM 128
#define GMAX 50000
#define CAP  192
#define OVF_MAX 4096

// ---------------- device scratch (zero-initialized .bss; self-restoring) ----------------
__device__ int g_cnt[GMAX];                 // per-segment node count (restored to 0 by pool)
__device__ int g_perm[(size_t)GMAX * CAP];  // bucketed node indices
__device__ int g_ovf[OVF_MAX];              // overflow node list (normally empty)
__device__ int g_novf;                      // overflow count (reset by pool's last block)
__device__ int g_is64;                      // seg dtype flag (written by scatter)
__device__ int g_done;                      // block-arrival ticket (reset by last block)

__device__ __forceinline__ float tanh_fast(float x) {
    float r;
    asm("tanh.approx.f32 %0, %1;" : "=f"(r) : "f"(x));
    return r;
}

// ---------------- kernel 1: scatter nodes into per-segment buckets ----------------
// 4 nodes per thread. Each block sniffs the seg dtype itself (L2-hit reads).
__global__ void __launch_bounds__(256) scatter_kernel(const void* __restrict__ seg, int N) {
    __shared__ int s_is64;
    if (threadIdx.x == 0) {
        // int64 ids < 2^32 have zero high words; 64 random int32 ids all-zero: p ~ 0
        const unsigned int* w = (const unsigned int*)seg;
        unsigned int acc = 0;
        #pragma unroll
        for (int k = 0; k < 64; k++) acc |= w[2 * k + 1];
        s_is64 = (acc == 0u) ? 1 : 0;
        if (blockIdx.x == 0) g_is64 = s_is64;
    }
    __syncthreads();
    const int is64 = s_is64;

    int base = (blockIdx.x * blockDim.x + threadIdx.x) * 4;
    if (base >= N) return;
    int cnt = min(4, N - base);

    int ids[4];
    if (cnt == 4) {
        if (is64) {
            const longlong2* p = (const longlong2*)((const long long*)seg + base);
            longlong2 v0 = __ldg(p), v1 = __ldg(p + 1);
            ids[0] = (int)v0.x; ids[1] = (int)v0.y; ids[2] = (int)v1.x; ids[3] = (int)v1.y;
        } else {
            int4 v = __ldg((const int4*)((const int*)seg + base));
            ids[0] = v.x; ids[1] = v.y; ids[2] = v.z; ids[3] = v.w;
        }
    } else {
        for (int j = 0; j < cnt; j++)
            ids[j] = is64 ? (int)((const long long*)seg)[base + j]
                          : ((const int*)seg)[base + j];
    }

    #pragma unroll
    for (int j = 0; j < 4; j++) {
        if (j >= cnt) break;
        int s = ids[j];
        int slot = atomicAdd(&g_cnt[s], 1);
        if (slot < CAP) {
            g_perm[(size_t)s * CAP + slot] = base + j;
        } else {
            int o = atomicAdd(&g_novf, 1);
            if (o < OVF_MAX) g_ovf[o] = base + j;
        }
    }
}

// ---------------- kernel 2: fused gather-pool + MLP ----------------
// 8 warps / block, one segment per warp for gather; block-cooperative GEMM
// epilogue with 4x W1 register reuse (warp -> 4 segments x 32 columns).
__global__ void __launch_bounds__(256) pool_mlp_kernel(
    const float* __restrict__ h,
    const void*  __restrict__ seg,
    const float* __restrict__ W1,   // [128,128] row-major: W1[k][c]
    const float* __restrict__ b1,   // [128]
    const float* __restrict__ W2,   // [128]
    const float* __restrict__ b2,   // [1]
    float* __restrict__ y, int G)
{
    __shared__ float sp[8][FDIM];   // pooled rows
    __shared__ float ssum[8][4];    // per-(seg, col-quarter) partial dots
    const int warp = threadIdx.x >> 5;
    const int lane = threadIdx.x & 31;
    const int gbase = blockIdx.x * 8;
    const int g = gbase + warp;
    const int nov = g_novf;         // read before any block can reset it

    // ---- gather + pool (one warp per segment) ----
    if (g < G) {
        const int n = g_cnt[g];
        if (lane == 0) g_cnt[g] = 0;            // self-restore for next replay
        const int nn = min(n, CAP);
        const int* pm = &g_perm[(size_t)g * CAP];

        float4 a0 = make_float4(0.f, 0.f, 0.f, 0.f);
        float4 a1 = a0, a2 = a0, a3 = a0;

        int i = 0;
        for (; i + 4 <= nn; i += 4) {
            int4 idx = __ldg((const int4*)(pm + i));
            float4 v0 = __ldcs((const float4*)(h + (size_t)idx.x * FDIM) + lane);
            float4 v1 = __ldcs((const float4*)(h + (size_t)idx.y * FDIM) + lane);
            float4 v2 = __ldcs((const float4*)(h + (size_t)idx.z * FDIM) + lane);
            float4 v3 = __ldcs((const float4*)(h + (size_t)idx.w * FDIM) + lane);
            a0.x += v0.x; a0.y += v0.y; a0.z += v0.z; a0.w += v0.w;
            a1.x += v1.x; a1.y += v1.y; a1.z += v1.z; a1.w += v1.w;
            a2.x += v2.x; a2.y += v2.y; a2.z += v2.z; a2.w += v2.w;
            a3.x += v3.x; a3.y += v3.y; a3.z += v3.z; a3.w += v3.w;
        }
        for (; i < nn; i++) {
            int nd = __ldg(pm + i);
            float4 v = __ldcs((const float4*)(h + (size_t)nd * FDIM) + lane);
            a0.x += v.x; a0.y += v.y; a0.z += v.z; a0.w += v.w;
        }

        // overflow path (correctness safety net; empty for real data)
        if (nov > 0) {
            const int m = min(nov, OVF_MAX);
            const int is64 = g_is64;
            for (int k = 0; k < m; k++) {
                int nd = g_ovf[k];
                int s = is64 ? (int)((const long long*)seg)[nd]
                             : ((const int*)seg)[nd];
                if (s == g) {
                    float4 v = __ldcs((const float4*)(h + (size_t)nd * FDIM) + lane);
                    a0.x += v.x; a0.y += v.y; a0.z += v.z; a0.w += v.w;
                }
            }
        }

        float4 acc;
        acc.x = (a0.x + a1.x) + (a2.x + a3.x);
        acc.y = (a0.y + a1.y) + (a2.y + a3.y);
        acc.z = (a0.z + a1.z) + (a2.z + a3.z);
        acc.w = (a0.w + a1.w) + (a2.w + a3.w);
        ((float4*)sp[warp])[lane] = acc;
    } else {
        ((float4*)sp[warp])[lane] = make_float4(0.f, 0.f, 0.f, 0.f);
    }
    __syncthreads();

    // ---- block GEMM epilogue: warp -> 4 segments x 32 columns ----
    const int sg = warp & 1;        // segment group: segs [4sg, 4sg+4)
    const int cq = warp >> 1;       // column quarter: cols [32cq, 32cq+32)
    const int c  = cq * 32 + lane;

    float bb = __ldg(b1 + c);
    float acc0 = bb, acc1 = bb, acc2 = bb, acc3 = bb;
    const float* s0 = sp[4 * sg + 0];
    const float* s1 = sp[4 * sg + 1];
    const float* s2 = sp[4 * sg + 2];
    const float* s3 = sp[4 * sg + 3];

    #pragma unroll 4
    for (int k = 0; k < FDIM; k++) {
        float wv = __ldg(W1 + k * FDIM + c);   // loaded once, used 4x
        acc0 = fmaf(s0[k], wv, acc0);
        acc1 = fmaf(s1[k], wv, acc1);
        acc2 = fmaf(s2[k], wv, acc2);
        acc3 = fmaf(s3[k], wv, acc3);
    }
    float w2 = __ldg(W2 + c);
    float p0 = tanh_fast(acc0) * w2;
    float p1 = tanh_fast(acc1) * w2;
    float p2 = tanh_fast(acc2) * w2;
    float p3 = tanh_fast(acc3) * w2;

    #pragma unroll
    for (int off = 16; off; off >>= 1) {
        p0 += __shfl_down_sync(0xffffffffu, p0, off);
        p1 += __shfl_down_sync(0xffffffffu, p1, off);
        p2 += __shfl_down_sync(0xffffffffu, p2, off);
        p3 += __shfl_down_sync(0xffffffffu, p3, off);
    }
    if (lane == 0) {
        ssum[4 * sg + 0][cq] = p0;
        ssum[4 * sg + 1][cq] = p1;
        ssum[4 * sg + 2][cq] = p2;
        ssum[4 * sg + 3][cq] = p3;
    }
    __syncthreads();

    if (warp == 0 && lane < 8) {
        int gg = gbase + lane;
        if (gg < G) {
            y[gg] = ssum[lane][0] + ssum[lane][1] + ssum[lane][2] + ssum[lane][3]
                  + __ldg(b2);
        }
    }

    // ---- elected last block resets overflow state for the next replay ----
    if (threadIdx.x == 0) {
        __threadfence();
        int t = atomicAdd(&g_done, 1);
        if (t == (int)gridDim.x - 1) {
            g_novf = 0;
            g_done = 0;
        }
    }
}

// ---------------- launch ----------------
extern "C" void kernel_launch(void* const* d_in, const int* in_sizes, int n_in,
                              void* d_out, int out_size) {
    const float* h   = (const float*)d_in[0];
    const void*  seg = d_in[1];
    const int N = in_sizes[0] / FDIM;
    const int G = out_size;          // OUT = 1

    int iw = -1;
    for (int i = 2; i < n_in; i++) {
        if (in_sizes[i] == FDIM * FDIM) { iw = i; break; }
    }
    const float* W1 = (const float*)d_in[iw];
    const float* b1 = (const float*)d_in[iw + 1];
    const float* W2 = (const float*)d_in[iw + 2];
    const float* b2 = (const float*)d_in[iw + 3];
    float* y = (float*)d_out;

    const int nodes_per_blk = 256 * 4;
    scatter_kernel<<<(N + nodes_per_blk - 1) / nodes_per_blk, 256>>>(seg, N);
    pool_mlp_kernel<<<(G + 7) / 8, 256>>>(h, seg, W1, b1, W2, b2, y, G);
}

// round 3
// speedup vs baseline: 1.2008x; 1.2008x over previous
#include <cuda_runtime.h>
#include <math.h>

#define FDIM 128
#define GMAX 50000
#define CAP  192
#define OVF_MAX 4096

// ---------------- device scratch (zero-initialized .bss; self-restoring) ----------------
__device__ int g_cnt[GMAX];                 // per-segment node count (restored to 0 by pool)
__device__ int g_perm[(size_t)GMAX * CAP];  // bucketed node indices
__device__ int g_ovf[OVF_MAX];              // overflow node list (normally empty)
__device__ int g_novf;                      // overflow count (reset by pool's last block)
__device__ int g_is64;                      // seg dtype flag (written by scatter)
__device__ int g_done;                      // block-arrival ticket (reset by last block)

__device__ __forceinline__ float tanh_fast(float x) {
    float r;
    asm("tanh.approx.f32 %0, %1;" : "=f"(r) : "f"(x));
    return r;
}

// ---------------- kernel 1: scatter nodes into per-segment buckets ----------------
__global__ void __launch_bounds__(256) scatter_kernel(const void* __restrict__ seg, int N) {
    __shared__ int s_is64;
    if (threadIdx.x == 0) {
        // int64 ids < 2^32 have zero high words; 64 random int32 ids all-zero: p ~ 0
        const unsigned int* w = (const unsigned int*)seg;
        unsigned int acc = 0;
        #pragma unroll
        for (int k = 0; k < 64; k++) acc |= w[2 * k + 1];
        s_is64 = (acc == 0u) ? 1 : 0;
        if (blockIdx.x == 0) g_is64 = s_is64;
    }
    __syncthreads();
    const int is64 = s_is64;

    int base = (blockIdx.x * blockDim.x + threadIdx.x) * 4;
    if (base >= N) return;
    int cnt = min(4, N - base);

    int ids[4];
    if (cnt == 4) {
        if (is64) {
            const longlong2* p = (const longlong2*)((const long long*)seg + base);
            longlong2 v0 = __ldg(p), v1 = __ldg(p + 1);
            ids[0] = (int)v0.x; ids[1] = (int)v0.y; ids[2] = (int)v1.x; ids[3] = (int)v1.y;
        } else {
            int4 v = __ldg((const int4*)((const int*)seg + base));
            ids[0] = v.x; ids[1] = v.y; ids[2] = v.z; ids[3] = v.w;
        }
    } else {
        for (int j = 0; j < cnt; j++)
            ids[j] = is64 ? (int)((const long long*)seg)[base + j]
                          : ((const int*)seg)[base + j];
    }

    #pragma unroll
    for (int j = 0; j < 4; j++) {
        if (j >= cnt) break;
        int s = ids[j];
        int slot = atomicAdd(&g_cnt[s], 1);
        if (slot < CAP) {
            g_perm[(size_t)s * CAP + slot] = base + j;
        } else {
            int o = atomicAdd(&g_novf, 1);
            if (o < OVF_MAX) g_ovf[o] = base + j;
        }
    }
}

// ---------------- warp-private gather of one segment into a float4 accumulator ----------------
__device__ __forceinline__ float4 gather_segment(
    const float* __restrict__ h, const void* __restrict__ seg,
    int g, int lane, int nov)
{
    const int n = g_cnt[g];
    if (lane == 0) g_cnt[g] = 0;                // self-restore for next replay
    const int nn = min(n, CAP);
    const int* pm = &g_perm[(size_t)g * CAP];

    float4 a0 = make_float4(0.f, 0.f, 0.f, 0.f);
    float4 a1 = a0, a2 = a0, a3 = a0;

    int i = 0;
    for (; i + 4 <= nn; i += 4) {
        int4 idx = __ldg((const int4*)(pm + i));
        float4 v0 = __ldcs((const float4*)(h + (size_t)idx.x * FDIM) + lane);
        float4 v1 = __ldcs((const float4*)(h + (size_t)idx.y * FDIM) + lane);
        float4 v2 = __ldcs((const float4*)(h + (size_t)idx.z * FDIM) + lane);
        float4 v3 = __ldcs((const float4*)(h + (size_t)idx.w * FDIM) + lane);
        a0.x += v0.x; a0.y += v0.y; a0.z += v0.z; a0.w += v0.w;
        a1.x += v1.x; a1.y += v1.y; a1.z += v1.z; a1.w += v1.w;
        a2.x += v2.x; a2.y += v2.y; a2.z += v2.z; a2.w += v2.w;
        a3.x += v3.x; a3.y += v3.y; a3.z += v3.z; a3.w += v3.w;
    }
    for (; i < nn; i++) {
        int nd = __ldg(pm + i);
        float4 v = __ldcs((const float4*)(h + (size_t)nd * FDIM) + lane);
        a0.x += v.x; a0.y += v.y; a0.z += v.z; a0.w += v.w;
    }

    if (nov > 0) {                              // correctness safety net (empty in practice)
        const int m = min(nov, OVF_MAX);
        const int is64 = g_is64;
        for (int k = 0; k < m; k++) {
            int nd = g_ovf[k];
            int s = is64 ? (int)((const long long*)seg)[nd]
                         : ((const int*)seg)[nd];
            if (s == g) {
                float4 v = __ldcs((const float4*)(h + (size_t)nd * FDIM) + lane);
                a0.x += v.x; a0.y += v.y; a0.z += v.z; a0.w += v.w;
            }
        }
    }

    float4 acc;
    acc.x = (a0.x + a1.x) + (a2.x + a3.x);
    acc.y = (a0.y + a1.y) + (a2.y + a3.y);
    acc.z = (a0.z + a1.z) + (a2.z + a3.z);
    acc.w = (a0.w + a1.w) + (a2.w + a3.w);
    return acc;
}

// ---------------- kernel 2: fused gather-pool + MLP ----------------
// Fully independent warps (no __syncthreads in the hot path).
// Each warp owns 2 segments: one W1 pass serves both GEMVs (2x L1 reuse).
__global__ void __launch_bounds__(256) pool_mlp_kernel(
    const float* __restrict__ h,
    const void*  __restrict__ seg,
    const float* __restrict__ W1,   // [128,128] row-major: W1[k][c]
    const float* __restrict__ b1,   // [128]
    const float* __restrict__ W2,   // [128]
    const float* __restrict__ b2,   // [1]
    float* __restrict__ y, int G)
{
    __shared__ float sp[8][2][FDIM];            // 2 pooled rows per warp (8 KB)
    const int warp = threadIdx.x >> 5;
    const int lane = threadIdx.x & 31;
    const int gA = (blockIdx.x * 8 + warp) * 2;
    const int gB = gA + 1;
    const int nov = g_novf;                     // read before any block resets it

    if (gA < G) {
        float4 accA = gather_segment(h, seg, gA, lane, nov);
        ((float4*)sp[warp][0])[lane] = accA;
    }
    bool hasB = (gB < G);
    if (hasB) {
        float4 accB = gather_segment(h, seg, gB, lane, nov);
        ((float4*)sp[warp][1])[lane] = accB;
    }
    __syncwarp();

    if (gA < G) {
        // hidden[4l..4l+3] = tanh(b1 + pooled @ W1) for both segments, sharing W1 loads
        float4 bb = __ldg((const float4*)b1 + lane);
        float hA0 = bb.x, hA1 = bb.y, hA2 = bb.z, hA3 = bb.w;
        float hB0 = bb.x, hB1 = bb.y, hB2 = bb.z, hB3 = bb.w;
        const float4* W1v = (const float4*)W1;          // row k, chunk lane
        const float* sA = sp[warp][0];
        const float* sB = sp[warp][1];

        #pragma unroll 4
        for (int k = 0; k < FDIM; k++) {
            float4 w = __ldg(W1v + k * 32 + lane);      // one load, two uses
            float pA = sA[k];
            float pB = sB[k];
            hA0 = fmaf(pA, w.x, hA0); hB0 = fmaf(pB, w.x, hB0);
            hA1 = fmaf(pA, w.y, hA1); hB1 = fmaf(pB, w.y, hB1);
            hA2 = fmaf(pA, w.z, hA2); hB2 = fmaf(pB, w.z, hB2);
            hA3 = fmaf(pA, w.w, hA3); hB3 = fmaf(pB, w.w, hB3);
        }

        float4 w2 = __ldg((const float4*)W2 + lane);
        float pA = tanh_fast(hA0) * w2.x + tanh_fast(hA1) * w2.y
                 + tanh_fast(hA2) * w2.z + tanh_fast(hA3) * w2.w;
        float pB = tanh_fast(hB0) * w2.x + tanh_fast(hB1) * w2.y
                 + tanh_fast(hB2) * w2.z + tanh_fast(hB3) * w2.w;

        #pragma unroll
        for (int off = 16; off; off >>= 1) {
            pA += __shfl_down_sync(0xffffffffu, pA, off);
            pB += __shfl_down_sync(0xffffffffu, pB, off);
        }
        if (lane == 0) {
            float bias = __ldg(b2);
            y[gA] = pA + bias;
            if (hasB) y[gB] = pB + bias;
        }
    }

    // ---- elected last block resets overflow state for the next replay ----
    if (threadIdx.x == 0) {
        __threadfence();
        int t = atomicAdd(&g_done, 1);
        if (t == (int)gridDim.x - 1) {
            g_novf = 0;
            g_done = 0;
        }
    }
}

// ---------------- launch ----------------
extern "C" void kernel_launch(void* const* d_in, const int* in_sizes, int n_in,
                              void* d_out, int out_size) {
    const float* h   = (const float*)d_in[0];
    const void*  seg = d_in[1];
    const int N = in_sizes[0] / FDIM;
    const int G = out_size;          // OUT = 1

    int iw = -1;
    for (int i = 2; i < n_in; i++) {
        if (in_sizes[i] == FDIM * FDIM) { iw = i; break; }
    }
    const float* W1 = (const float*)d_in[iw];
    const float* b1 = (const float*)d_in[iw + 1];
    const float* W2 = (const float*)d_in[iw + 2];
    const float* b2 = (const float*)d_in[iw + 3];
    float* y = (float*)d_out;

    const int nodes_per_blk = 256 * 4;
    scatter_kernel<<<(N + nodes_per_blk - 1) / nodes_per_blk, 256>>>(seg, N);
    const int segs_per_blk = 16;     // 8 warps x 2 segments
    pool_mlp_kernel<<<(G + segs_per_blk - 1) / segs_per_blk, 256>>>(h, seg, W1, b1, W2, b2, y, G);
}